// round 1
// baseline (speedup 1.0000x reference)
#include <cuda_runtime.h>
#include <cuda_bf16.h>
#include <math.h>

// ---------------------------------------------------------------------------
// Swin Transformer block, fp32 baseline.
// B=32, H=W=56, DIM=256, HEADS=8, WS=7, SHIFT=3, N=49, NW=64, HEAD_DIM=32,
// HIDDEN=1024. Tokens = 32*56*56 = 100352.
// ---------------------------------------------------------------------------

#define TOK      100352
#define DIM      256
#define HIDDEN   1024
#define QKVDIM   768
#define HEADS    8
#define HEAD_DIM 32
#define NTOK     49      // tokens per window
#define NWIN     64      // windows per image
#define HW       3136    // 56*56
#define SHIFT    3

// Scratch (device globals: no allocations allowed)
__device__ float g_hwin[(size_t)TOK * DIM];    //  98 MB : LN1 output, windowed layout
__device__ float g_qkv [(size_t)TOK * QKVDIM]; // 294 MB : qkv
__device__ float g_attn[(size_t)TOK * DIM];    //  98 MB : attention output (window layout)
__device__ float g_x2  [(size_t)TOK * DIM];    //  98 MB : x + proj (spatial layout)
__device__ float g_h2  [(size_t)TOK * DIM];    //  98 MB : LN2 output
__device__ float g_hbuf[(size_t)TOK * HIDDEN]; // 411 MB : gelu(fc1) output

// ---------------------------------------------------------------------------
// LayerNorm. REMAP=true: gather with cyclic shift + window partition (LN1).
// One warp per token row. blockDim=256 (8 warps).
// ---------------------------------------------------------------------------
template <bool REMAP>
__global__ void ln_kernel(const float* __restrict__ in,
                          const float* __restrict__ w,
                          const float* __restrict__ b,
                          float* __restrict__ out)
{
    int warp = threadIdx.x >> 5;
    int lane = threadIdx.x & 31;
    int row  = blockIdx.x * 8 + warp;   // window-token index (< TOK)

    const float* src;
    if (REMAP) {
        int bz = row / HW;
        int r  = row - bz * HW;
        int wI = r / NTOK;
        int t2 = r - wI * NTOK;
        int wh = wI >> 3, ww = wI & 7;
        int i  = t2 / 7,  j  = t2 - (t2 / 7) * 7;
        int sh = (wh * 7 + i + SHIFT) % 56;
        int sw = (ww * 7 + j + SHIFT) % 56;
        src = in + ((size_t)bz * HW + sh * 56 + sw) * DIM;
    } else {
        src = in + (size_t)row * DIM;
    }

    float v[8];
    float s = 0.f, ss = 0.f;
#pragma unroll
    for (int k = 0; k < 8; k++) {
        v[k] = src[lane + 32 * k];
        s  += v[k];
        ss += v[k] * v[k];
    }
#pragma unroll
    for (int o = 16; o; o >>= 1) {
        s  += __shfl_xor_sync(0xffffffffu, s,  o);
        ss += __shfl_xor_sync(0xffffffffu, ss, o);
    }
    float mu   = s * (1.f / DIM);
    float var  = ss * (1.f / DIM) - mu * mu;
    float rstd = rsqrtf(var + 1e-5f);

    float* dst = out + (size_t)row * DIM;
#pragma unroll
    for (int k = 0; k < 8; k++) {
        int c = lane + 32 * k;
        dst[c] = (v[k] - mu) * rstd * w[c] + b[c];
    }
}

// ---------------------------------------------------------------------------
// Tiled fp32 GEMM: C[m,n] = sum_k A[m,k] * W[n,k]  (+ epilogue)
// A: [M,K] row-major, W: [N,K] row-major. BM=BN=128, BK=8, 256 threads, 8x8/thr.
// All dims divisible: no bounds checks.
// EPI: 0 = +bias (qkv)
//      1 = +bias, window-reverse scatter + residual with x (proj)   Ntot=256
//      2 = +bias then exact GELU (fc1)
//      3 = +bias + residual(extra) final write (fc2)
// ---------------------------------------------------------------------------
template <int EPI>
__global__ void __launch_bounds__(256)
gemm128(const float* __restrict__ A, const float* __restrict__ W,
        const float* __restrict__ bias, const float* __restrict__ extra,
        float* __restrict__ out, int K, int Ntot)
{
    __shared__ float As[8][128];
    __shared__ float Bs[8][128];

    int tid = threadIdx.x;
    int m0  = blockIdx.y * 128;
    int n0  = blockIdx.x * 128;

    int lr = tid >> 1;            // 0..127
    int lc = (tid & 1) << 2;      // 0 or 4
    const float* Ap = A + (size_t)(m0 + lr) * K + lc;
    const float* Wp = W + (size_t)(n0 + lr) * K + lc;

    int trow = (tid >> 4) << 3;   // 0..120
    int tcol = (tid & 15) << 3;   // 0..120

    float acc[8][8];
#pragma unroll
    for (int i = 0; i < 8; i++)
#pragma unroll
        for (int j = 0; j < 8; j++) acc[i][j] = 0.f;

    for (int k0 = 0; k0 < K; k0 += 8) {
        float4 a4 = *(const float4*)(Ap + k0);
        float4 w4 = *(const float4*)(Wp + k0);
        As[lc + 0][lr] = a4.x; As[lc + 1][lr] = a4.y;
        As[lc + 2][lr] = a4.z; As[lc + 3][lr] = a4.w;
        Bs[lc + 0][lr] = w4.x; Bs[lc + 1][lr] = w4.y;
        Bs[lc + 2][lr] = w4.z; Bs[lc + 3][lr] = w4.w;
        __syncthreads();
#pragma unroll
        for (int k = 0; k < 8; k++) {
            float4 a0 = *(const float4*)&As[k][trow];
            float4 a1 = *(const float4*)&As[k][trow + 4];
            float4 b0 = *(const float4*)&Bs[k][tcol];
            float4 b1 = *(const float4*)&Bs[k][tcol + 4];
            float ar[8] = {a0.x, a0.y, a0.z, a0.w, a1.x, a1.y, a1.z, a1.w};
            float br[8] = {b0.x, b0.y, b0.z, b0.w, b1.x, b1.y, b1.z, b1.w};
#pragma unroll
            for (int i = 0; i < 8; i++)
#pragma unroll
                for (int j = 0; j < 8; j++)
                    acc[i][j] += ar[i] * br[j];
        }
        __syncthreads();
    }

    // epilogue
#pragma unroll
    for (int i = 0; i < 8; i++) {
        int row = m0 + trow + i;
        if (EPI == 0) {
            float* o = out + (size_t)row * Ntot + n0 + tcol;
#pragma unroll
            for (int j = 0; j < 8; j++) o[j] = acc[i][j] + bias[n0 + tcol + j];
        } else if (EPI == 1) {
            // window-reverse + un-shift scatter with residual
            int bz = row / HW;
            int r  = row - bz * HW;
            int wI = r / NTOK;
            int t2 = r - wI * NTOK;
            int wh = wI >> 3, ww = wI & 7;
            int ii = t2 / 7,  jj = t2 - (t2 / 7) * 7;
            int sh = (wh * 7 + ii + SHIFT) % 56;
            int sw = (ww * 7 + jj + SHIFT) % 56;
            size_t dst = ((size_t)bz * HW + sh * 56 + sw) * DIM + n0 + tcol;
#pragma unroll
            for (int j = 0; j < 8; j++)
                out[dst + j] = extra[dst + j] + acc[i][j] + bias[n0 + tcol + j];
        } else if (EPI == 2) {
            float* o = out + (size_t)row * Ntot + n0 + tcol;
#pragma unroll
            for (int j = 0; j < 8; j++) {
                float v = acc[i][j] + bias[n0 + tcol + j];
                o[j] = 0.5f * v * (1.f + erff(v * 0.70710678118654752f));
            }
        } else {
            size_t off = (size_t)row * Ntot + n0 + tcol;
#pragma unroll
            for (int j = 0; j < 8; j++)
                out[off + j] = acc[i][j] + bias[n0 + tcol + j] + extra[off + j];
        }
    }
}

// ---------------------------------------------------------------------------
// Windowed attention: one block per (window, head). 2048 windows * 8 heads.
// q/k/v tiles 49x32 in padded smem, scores 49x49, warp-per-row softmax.
// ---------------------------------------------------------------------------
__global__ void __launch_bounds__(128)
attn_kernel(const float* __restrict__ qkv, const float* __restrict__ rpb,
            const int* __restrict__ relidx, const float* __restrict__ mask,
            float* __restrict__ out)
{
    __shared__ float qs[NTOK][33];
    __shared__ float ks[NTOK][33];
    __shared__ float vs[NTOK][33];
    __shared__ float ss[NTOK][50];
    __shared__ float rpb_s[169];

    int blk  = blockIdx.x;
    int head = blk & 7;
    int win  = blk >> 3;
    int tid  = threadIdx.x;

    const float* base = qkv + (size_t)win * NTOK * QKVDIM + head * HEAD_DIM;

    for (int idx = tid; idx < NTOK * 8; idx += 128) {
        int n  = idx >> 3;
        int c4 = (idx & 7) << 2;
        const float* p = base + (size_t)n * QKVDIM + c4;
        float4 q4 = *(const float4*)(p);
        float4 k4 = *(const float4*)(p + 256);
        float4 v4 = *(const float4*)(p + 512);
        qs[n][c4+0]=q4.x; qs[n][c4+1]=q4.y; qs[n][c4+2]=q4.z; qs[n][c4+3]=q4.w;
        ks[n][c4+0]=k4.x; ks[n][c4+1]=k4.y; ks[n][c4+2]=k4.z; ks[n][c4+3]=k4.w;
        vs[n][c4+0]=v4.x; vs[n][c4+1]=v4.y; vs[n][c4+2]=v4.z; vs[n][c4+3]=v4.w;
    }
    for (int i = tid; i < 169; i += 128) rpb_s[i] = rpb[i * HEADS + head];
    __syncthreads();

    const float scale = 0.17677669529663687f; // 1/sqrt(32)
    const float* mrow = mask + (size_t)(win & 63) * (NTOK * NTOK);

    for (int ij = tid; ij < NTOK * NTOK; ij += 128) {
        int i = ij / NTOK;
        int j = ij - i * NTOK;
        float acc = 0.f;
#pragma unroll
        for (int c = 0; c < HEAD_DIM; c++) acc += qs[i][c] * ks[j][c];
        ss[i][j] = acc * scale + rpb_s[relidx[ij]] + mrow[ij];
    }
    __syncthreads();

    int warp = tid >> 5, lane = tid & 31;
    for (int r = warp; r < NTOK; r += 4) {
        float a  = ss[r][lane];
        bool  hi = (lane + 32) < NTOK;
        float b  = hi ? ss[r][lane + 32] : -1e30f;
        float mx = fmaxf(a, b);
#pragma unroll
        for (int o = 16; o; o >>= 1) mx = fmaxf(mx, __shfl_xor_sync(0xffffffffu, mx, o));
        float e0 = expf(a - mx);
        float e1 = hi ? expf(b - mx) : 0.f;
        float sm = e0 + e1;
#pragma unroll
        for (int o = 16; o; o >>= 1) sm += __shfl_xor_sync(0xffffffffu, sm, o);
        float inv = 1.f / sm;
        ss[r][lane] = e0 * inv;
        if (hi) ss[r][lane + 32] = e1 * inv;
    }
    __syncthreads();

    for (int idx = tid; idx < NTOK * HEAD_DIM; idx += 128) {
        int i  = idx >> 5;
        int dd = idx & 31;
        float acc = 0.f;
#pragma unroll
        for (int j = 0; j < NTOK; j++) acc += ss[i][j] * vs[j][dd];
        out[((size_t)win * NTOK + i) * DIM + head * HEAD_DIM + dd] = acc;
    }
}

// ---------------------------------------------------------------------------
extern "C" void kernel_launch(void* const* d_in, const int* in_sizes, int n_in,
                              void* d_out, int out_size)
{
    const float* x     = (const float*)d_in[0];
    const float* n1w   = (const float*)d_in[1];
    const float* n1b   = (const float*)d_in[2];
    const float* qkvw  = (const float*)d_in[3];
    const float* qkvb  = (const float*)d_in[4];
    const float* rpb   = (const float*)d_in[5];
    const float* projw = (const float*)d_in[6];
    const float* projb = (const float*)d_in[7];
    const float* n2w   = (const float*)d_in[8];
    const float* n2b   = (const float*)d_in[9];
    const float* fc1w  = (const float*)d_in[10];
    const float* fc1b  = (const float*)d_in[11];
    const float* fc2w  = (const float*)d_in[12];
    const float* fc2b  = (const float*)d_in[13];
    const int*   ridx  = (const int*)d_in[14];
    const float* amask = (const float*)d_in[15];
    float* outp = (float*)d_out;

    float *hwin, *qkv, *attn, *x2, *h2, *hbuf;
    cudaGetSymbolAddress((void**)&hwin, g_hwin);
    cudaGetSymbolAddress((void**)&qkv,  g_qkv);
    cudaGetSymbolAddress((void**)&attn, g_attn);
    cudaGetSymbolAddress((void**)&x2,   g_x2);
    cudaGetSymbolAddress((void**)&h2,   g_h2);
    cudaGetSymbolAddress((void**)&hbuf, g_hbuf);

    // 1. LN1 fused with shift + window partition
    ln_kernel<true><<<TOK / 8, 256>>>(x, n1w, n1b, hwin);
    // 2. QKV GEMM: [TOK,256] x [768,256]^T
    gemm128<0><<<dim3(QKVDIM / 128, TOK / 128), 256>>>(hwin, qkvw, qkvb, nullptr, qkv, DIM, QKVDIM);
    // 3. windowed attention
    attn_kernel<<<2048 * HEADS, 128>>>(qkv, rpb, ridx, amask, attn);
    // 4. proj GEMM + window-reverse scatter + residual -> x2
    gemm128<1><<<dim3(DIM / 128, TOK / 128), 256>>>(attn, projw, projb, x, x2, DIM, DIM);
    // 5. LN2
    ln_kernel<false><<<TOK / 8, 256>>>(x2, n2w, n2b, h2);
    // 6. FC1 + GELU
    gemm128<2><<<dim3(HIDDEN / 128, TOK / 128), 256>>>(h2, fc1w, fc1b, nullptr, hbuf, DIM, HIDDEN);
    // 7. FC2 + bias + residual -> final output
    gemm128<3><<<dim3(DIM / 128, TOK / 128), 256>>>(hbuf, fc2w, fc2b, x2, outp, HIDDEN, DIM);
}

// round 7
// speedup vs baseline: 3.7326x; 3.7326x over previous
#include <cuda_runtime.h>
#include <cuda_bf16.h>
#include <math.h>
#include <stdint.h>

// ---------------------------------------------------------------------------
// Swin block: GEMMs via mma.sync bf16 (fp32 accum), attention/LN fp32.
// B=32, H=W=56, DIM=256, HEADS=8, WS=7, SHIFT=3, N=49, NW=64, HEAD_DIM=32.
// NOTE: harness PTX targets plain sm_103 (no 'a') -> tcgen05 unavailable;
// mma.sync/ldmatrix/cp.async are the fastest available tensor path.
// ---------------------------------------------------------------------------

#define TOK      100352
#define DIM      256
#define HIDDEN   1024
#define QKVDIM   768
#define HEADS    8
#define HEAD_DIM 32
#define NTOK     49
#define HW       3136
#define SHIFT    3

typedef __nv_bfloat16 bf16;

// ------------------------- scratch (device globals) ------------------------
__device__ __align__(16) bf16  g_hwin_b[(size_t)TOK * DIM];
__device__ __align__(16) float g_qkv   [(size_t)TOK * QKVDIM];
__device__ __align__(16) bf16  g_attn_b[(size_t)TOK * DIM];
__device__ __align__(16) float g_x2    [(size_t)TOK * DIM];
__device__ __align__(16) bf16  g_h2_b  [(size_t)TOK * DIM];
__device__ __align__(16) bf16  g_hbuf_b[(size_t)TOK * HIDDEN];
__device__ __align__(16) bf16  g_wqkv_b [QKVDIM * DIM];
__device__ __align__(16) bf16  g_wproj_b[DIM * DIM];
__device__ __align__(16) bf16  g_wfc1_b [HIDDEN * DIM];
__device__ __align__(16) bf16  g_wfc2_b [DIM * HIDDEN];

// ------------------------------ PTX helpers --------------------------------
__device__ __forceinline__ uint32_t smem_u32(const void* p) {
    uint32_t a;
    asm("{ .reg .u64 t; cvta.to.shared.u64 t, %1; cvt.u32.u64 %0, t; }"
        : "=r"(a) : "l"(p));
    return a;
}
__device__ __forceinline__ void cp_async16(uint32_t dst, const void* src) {
    asm volatile("cp.async.cg.shared.global [%0], [%1], 16;"
                 :: "r"(dst), "l"(src));
}
#define CP_COMMIT() asm volatile("cp.async.commit_group;")
#define CP_WAIT(n)  asm volatile("cp.async.wait_group %0;" :: "n"(n))

__device__ __forceinline__ void ldsm_x4(uint32_t& r0, uint32_t& r1,
                                        uint32_t& r2, uint32_t& r3, uint32_t a) {
    asm volatile("ldmatrix.sync.aligned.m8n8.x4.shared.b16 {%0,%1,%2,%3}, [%4];"
                 : "=r"(r0), "=r"(r1), "=r"(r2), "=r"(r3) : "r"(a));
}
__device__ __forceinline__ void mma16816(float* d, const uint32_t* a,
                                         const uint32_t* b) {
    asm volatile(
        "mma.sync.aligned.m16n8k16.row.col.f32.bf16.bf16.f32 "
        "{%0,%1,%2,%3}, {%4,%5,%6,%7}, {%8,%9}, {%0,%1,%2,%3};"
        : "+f"(d[0]), "+f"(d[1]), "+f"(d[2]), "+f"(d[3])
        : "r"(a[0]), "r"(a[1]), "r"(a[2]), "r"(a[3]), "r"(b[0]), "r"(b[1]));
}

// ---------------------------------------------------------------------------
// LayerNorm -> bf16. REMAP: gather with cyclic shift + window partition.
// ---------------------------------------------------------------------------
template <bool REMAP>
__global__ void ln_kernel(const float* __restrict__ in,
                          const float* __restrict__ w,
                          const float* __restrict__ b,
                          bf16* __restrict__ out)
{
    int warp = threadIdx.x >> 5;
    int lane = threadIdx.x & 31;
    int row  = blockIdx.x * 8 + warp;

    const float* src;
    if (REMAP) {
        int bz = row / HW;
        int r  = row - bz * HW;
        int wI = r / NTOK;
        int t2 = r - wI * NTOK;
        int wh = wI >> 3, ww = wI & 7;
        int i  = t2 / 7,  j  = t2 - (t2 / 7) * 7;
        int sh = (wh * 7 + i + SHIFT) % 56;
        int sw = (ww * 7 + j + SHIFT) % 56;
        src = in + ((size_t)bz * HW + sh * 56 + sw) * DIM;
    } else {
        src = in + (size_t)row * DIM;
    }

    float v[8];
    float s = 0.f, ss = 0.f;
#pragma unroll
    for (int k = 0; k < 8; k++) {
        v[k] = src[lane + 32 * k];
        s  += v[k];
        ss += v[k] * v[k];
    }
#pragma unroll
    for (int o = 16; o; o >>= 1) {
        s  += __shfl_xor_sync(0xffffffffu, s,  o);
        ss += __shfl_xor_sync(0xffffffffu, ss, o);
    }
    float mu   = s * (1.f / DIM);
    float var  = ss * (1.f / DIM) - mu * mu;
    float rstd = rsqrtf(var + 1e-5f);

    bf16* dst = out + (size_t)row * DIM;
#pragma unroll
    for (int k = 0; k < 8; k++) {
        int c = lane + 32 * k;
        dst[c] = __float2bfloat16((v[k] - mu) * rstd * w[c] + b[c]);
    }
}

__global__ void cvt_kernel(const float* __restrict__ in,
                           bf16* __restrict__ out, int n)
{
    int i = blockIdx.x * 256 + threadIdx.x;
    if (i < n) out[i] = __float2bfloat16(in[i]);
}

// ---------------------------------------------------------------------------
// bf16 mma.sync GEMM: C[m,n] = sum_k A[m,k]*W[n,k] (+ epilogue)
// BM=BN=128, BK=32, 256 thr (warp grid 2x4; 64x32 per warp), 2-stage cp.async.
// EPI: 0 qkv(+bias)  1 proj(+bias,scatter+residual)  2 fc1(+bias,gelu->bf16)
//      3 fc2(+bias+residual)
// ---------------------------------------------------------------------------
#define STRIDE 40   // bf16 per smem row (32 + 8 pad)

template <int EPI>
__global__ void __launch_bounds__(256)
gemm_mma(const bf16* __restrict__ A, const bf16* __restrict__ W,
         const float* __restrict__ bias, const float* __restrict__ extra,
         float* __restrict__ out, bf16* __restrict__ outb,
         int K, int Ntot)
{
    __shared__ bf16 As[2][128][STRIDE];
    __shared__ bf16 Bs[2][128][STRIDE];

    int tid    = threadIdx.x;
    int lane   = tid & 31;
    int wid    = tid >> 5;
    int warp_m = wid & 1;          // 0..1 (64 rows each)
    int warp_n = wid >> 1;         // 0..3 (32 cols each)
    int m0     = blockIdx.y * 128;
    int n0     = blockIdx.x * 128;

    // cp.async load coords: 512 16B chunks per tile, 2 per thread
    int lr = tid >> 2;             // 0..63 base row (+64 on second pass)
    int lc = (tid & 3) << 3;       // bf16 col: 0,8,16,24

    float c[4][4][4];
#pragma unroll
    for (int i = 0; i < 4; i++)
#pragma unroll
        for (int j = 0; j < 4; j++)
#pragma unroll
            for (int k = 0; k < 4; k++) c[i][j][k] = 0.f;

    int nk = K >> 5;

    // prologue: stage 0
    {
#pragma unroll
        for (int t = 0; t < 2; t++) {
            int r = lr + t * 64;
            cp_async16(smem_u32(&As[0][r][lc]), A + (size_t)(m0 + r) * K + lc);
            cp_async16(smem_u32(&Bs[0][r][lc]), W + (size_t)(n0 + r) * K + lc);
        }
        CP_COMMIT();
    }

    // ldmatrix lane addressing
    int a_row  = warp_m * 64 + (lane & 15);          // + mt*16
    int a_koff = (lane >> 4) << 3;                   // + ks*16
    int b_row0 = warp_n * 32 + (lane & 7) + ((lane >> 4) << 3); // + nt*16
    int b_koff = ((lane >> 3) & 1) << 3;             // + ks*16

    for (int kk = 0; kk < nk; kk++) {
        int st = kk & 1;
        if (kk + 1 < nk) {
            int kb = (kk + 1) << 5;
#pragma unroll
            for (int t = 0; t < 2; t++) {
                int r = lr + t * 64;
                cp_async16(smem_u32(&As[st ^ 1][r][lc]),
                           A + (size_t)(m0 + r) * K + kb + lc);
                cp_async16(smem_u32(&Bs[st ^ 1][r][lc]),
                           W + (size_t)(n0 + r) * K + kb + lc);
            }
            CP_COMMIT();
            CP_WAIT(1);
        } else {
            CP_WAIT(0);
        }
        __syncthreads();

#pragma unroll
        for (int ks = 0; ks < 2; ks++) {
            uint32_t a[4][4];
            uint32_t b[4][2];
#pragma unroll
            for (int mt = 0; mt < 4; mt++)
                ldsm_x4(a[mt][0], a[mt][1], a[mt][2], a[mt][3],
                        smem_u32(&As[st][a_row + mt * 16][ks * 16 + a_koff]));
#pragma unroll
            for (int np = 0; np < 2; np++)
                ldsm_x4(b[np * 2][0], b[np * 2][1], b[np * 2 + 1][0], b[np * 2 + 1][1],
                        smem_u32(&Bs[st][b_row0 + np * 16][ks * 16 + b_koff]));
#pragma unroll
            for (int mt = 0; mt < 4; mt++)
#pragma unroll
                for (int nt = 0; nt < 4; nt++)
                    mma16816(c[mt][nt], a[mt], b[nt]);
        }
        __syncthreads();
    }

    // ------------------------------- epilogue -------------------------------
    int gid = lane >> 2;   // 0..7 row in tile
    int qid = lane & 3;    // col pair

#pragma unroll
    for (int mt = 0; mt < 4; mt++) {
        int r0 = m0 + warp_m * 64 + mt * 16 + gid;
        int r1 = r0 + 8;
        size_t base0, base1;
        if (EPI == 1) {
#pragma unroll
            for (int h = 0; h < 2; h++) {
                int row = h ? r1 : r0;
                int bz = row / HW;
                int r  = row - bz * HW;
                int wI = r / NTOK;
                int t2 = r - wI * NTOK;
                int wh = wI >> 3, ww = wI & 7;
                int ii = t2 / 7,  jj = t2 - (t2 / 7) * 7;
                int sh = (wh * 7 + ii + SHIFT) % 56;
                int sw = (ww * 7 + jj + SHIFT) % 56;
                size_t d = ((size_t)bz * HW + sh * 56 + sw) * DIM;
                if (h) base1 = d; else base0 = d;
            }
        } else {
            base0 = (size_t)r0 * Ntot;
            base1 = (size_t)r1 * Ntot;
        }
#pragma unroll
        for (int nt = 0; nt < 4; nt++) {
            int col = n0 + warp_n * 32 + nt * 8 + qid * 2;
            float b0 = bias[col], b1 = bias[col + 1];
            float v00 = c[mt][nt][0] + b0, v01 = c[mt][nt][1] + b1;
            float v10 = c[mt][nt][2] + b0, v11 = c[mt][nt][3] + b1;
            if (EPI == 0) {
                *(float2*)(out + base0 + col) = make_float2(v00, v01);
                *(float2*)(out + base1 + col) = make_float2(v10, v11);
            } else if (EPI == 1) {
                out[base0 + col]     = v00 + extra[base0 + col];
                out[base0 + col + 1] = v01 + extra[base0 + col + 1];
                out[base1 + col]     = v10 + extra[base1 + col];
                out[base1 + col + 1] = v11 + extra[base1 + col + 1];
            } else if (EPI == 2) {
                const float isq2 = 0.70710678118654752f;
                float g00 = 0.5f * v00 * (1.f + erff(v00 * isq2));
                float g01 = 0.5f * v01 * (1.f + erff(v01 * isq2));
                float g10 = 0.5f * v10 * (1.f + erff(v10 * isq2));
                float g11 = 0.5f * v11 * (1.f + erff(v11 * isq2));
                *(__nv_bfloat162*)(outb + base0 + col) =
                    __nv_bfloat162(__float2bfloat16(g00), __float2bfloat16(g01));
                *(__nv_bfloat162*)(outb + base1 + col) =
                    __nv_bfloat162(__float2bfloat16(g10), __float2bfloat16(g11));
            } else {
                *(float2*)(out + base0 + col) =
                    make_float2(v00 + extra[base0 + col], v01 + extra[base0 + col + 1]);
                *(float2*)(out + base1 + col) =
                    make_float2(v10 + extra[base1 + col], v11 + extra[base1 + col + 1]);
            }
        }
    }
}

// ---------------------------------------------------------------------------
// Windowed attention (fp32), bf16 out. One block per (window, head).
// ---------------------------------------------------------------------------
__global__ void __launch_bounds__(128)
attn_kernel(const float* __restrict__ qkv, const float* __restrict__ rpb,
            const int* __restrict__ relidx, const float* __restrict__ mask,
            bf16* __restrict__ out)
{
    __shared__ float qs[NTOK][33];
    __shared__ float ks[NTOK][33];
    __shared__ float vs[NTOK][33];
    __shared__ float ss[NTOK][50];
    __shared__ float rpb_s[169];

    int blk  = blockIdx.x;
    int head = blk & 7;
    int win  = blk >> 3;
    int tid  = threadIdx.x;

    const float* base = qkv + (size_t)win * NTOK * QKVDIM + head * HEAD_DIM;

    for (int idx = tid; idx < NTOK * 8; idx += 128) {
        int n  = idx >> 3;
        int c4 = (idx & 7) << 2;
        const float* p = base + (size_t)n * QKVDIM + c4;
        float4 q4 = *(const float4*)(p);
        float4 k4 = *(const float4*)(p + 256);
        float4 v4 = *(const float4*)(p + 512);
        qs[n][c4+0]=q4.x; qs[n][c4+1]=q4.y; qs[n][c4+2]=q4.z; qs[n][c4+3]=q4.w;
        ks[n][c4+0]=k4.x; ks[n][c4+1]=k4.y; ks[n][c4+2]=k4.z; ks[n][c4+3]=k4.w;
        vs[n][c4+0]=v4.x; vs[n][c4+1]=v4.y; vs[n][c4+2]=v4.z; vs[n][c4+3]=v4.w;
    }
    for (int i = tid; i < 169; i += 128) rpb_s[i] = rpb[i * HEADS + head];
    __syncthreads();

    const float scale = 0.17677669529663687f;
    const float* mrow = mask + (size_t)(win & 63) * (NTOK * NTOK);

    for (int ij = tid; ij < NTOK * NTOK; ij += 128) {
        int i = ij / NTOK;
        int j = ij - i * NTOK;
        float acc = 0.f;
#pragma unroll
        for (int cc = 0; cc < HEAD_DIM; cc++) acc += qs[i][cc] * ks[j][cc];
        ss[i][j] = acc * scale + rpb_s[relidx[ij]] + mrow[ij];
    }
    __syncthreads();

    int warp = tid >> 5, lane = tid & 31;
    for (int r = warp; r < NTOK; r += 4) {
        float a  = ss[r][lane];
        bool  hi = (lane + 32) < NTOK;
        float b  = hi ? ss[r][lane + 32] : -1e30f;
        float mx = fmaxf(a, b);
#pragma unroll
        for (int o = 16; o; o >>= 1) mx = fmaxf(mx, __shfl_xor_sync(0xffffffffu, mx, o));
        float e0 = expf(a - mx);
        float e1 = hi ? expf(b - mx) : 0.f;
        float sm = e0 + e1;
#pragma unroll
        for (int o = 16; o; o >>= 1) sm += __shfl_xor_sync(0xffffffffu, sm, o);
        float inv = 1.f / sm;
        ss[r][lane] = e0 * inv;
        if (hi) ss[r][lane + 32] = e1 * inv;
    }
    __syncthreads();

    for (int idx = tid; idx < NTOK * HEAD_DIM; idx += 128) {
        int i  = idx >> 5;
        int dd = idx & 31;
        float acc = 0.f;
#pragma unroll
        for (int j = 0; j < NTOK; j++) acc += ss[i][j] * vs[j][dd];
        out[((size_t)win * NTOK + i) * DIM + head * HEAD_DIM + dd] = __float2bfloat16(acc);
    }
}

// ---------------------------------------------------------------------------
extern "C" void kernel_launch(void* const* d_in, const int* in_sizes, int n_in,
                              void* d_out, int out_size)
{
    const float* x     = (const float*)d_in[0];
    const float* n1w   = (const float*)d_in[1];
    const float* n1b   = (const float*)d_in[2];
    const float* qkvw  = (const float*)d_in[3];
    const float* qkvb  = (const float*)d_in[4];
    const float* rpb   = (const float*)d_in[5];
    const float* projw = (const float*)d_in[6];
    const float* projb = (const float*)d_in[7];
    const float* n2w   = (const float*)d_in[8];
    const float* n2b   = (const float*)d_in[9];
    const float* fc1w  = (const float*)d_in[10];
    const float* fc1b  = (const float*)d_in[11];
    const float* fc2w  = (const float*)d_in[12];
    const float* fc2b  = (const float*)d_in[13];
    const int*   ridx  = (const int*)d_in[14];
    const float* amask = (const float*)d_in[15];
    float* outp = (float*)d_out;

    bf16 *hwin, *attnb, *h2b, *hbufb, *wqkv, *wproj, *wfc1, *wfc2;
    float *qkv, *x2;
    cudaGetSymbolAddress((void**)&hwin,  g_hwin_b);
    cudaGetSymbolAddress((void**)&qkv,   g_qkv);
    cudaGetSymbolAddress((void**)&attnb, g_attn_b);
    cudaGetSymbolAddress((void**)&x2,    g_x2);
    cudaGetSymbolAddress((void**)&h2b,   g_h2_b);
    cudaGetSymbolAddress((void**)&hbufb, g_hbuf_b);
    cudaGetSymbolAddress((void**)&wqkv,  g_wqkv_b);
    cudaGetSymbolAddress((void**)&wproj, g_wproj_b);
    cudaGetSymbolAddress((void**)&wfc1,  g_wfc1_b);
    cudaGetSymbolAddress((void**)&wfc2,  g_wfc2_b);

    // weight conversion
    cvt_kernel<<<(QKVDIM * DIM + 255) / 256, 256>>>(qkvw,  wqkv,  QKVDIM * DIM);
    cvt_kernel<<<(DIM * DIM + 255) / 256, 256>>>(projw, wproj, DIM * DIM);
    cvt_kernel<<<(HIDDEN * DIM + 255) / 256, 256>>>(fc1w,  wfc1,  HIDDEN * DIM);
    cvt_kernel<<<(DIM * HIDDEN + 255) / 256, 256>>>(fc2w,  wfc2,  DIM * HIDDEN);

    // 1. LN1 + shift + window partition -> bf16
    ln_kernel<true><<<TOK / 8, 256>>>(x, n1w, n1b, hwin);
    // 2. QKV GEMM [TOK,256] x [768,256]^T -> fp32
    gemm_mma<0><<<dim3(QKVDIM / 128, TOK / 128), 256>>>(
        hwin, wqkv, qkvb, nullptr, qkv, nullptr, DIM, QKVDIM);
    // 3. windowed attention -> bf16
    attn_kernel<<<2048 * HEADS, 128>>>(qkv, rpb, ridx, amask, attnb);
    // 4. proj GEMM + window-reverse scatter + residual -> x2
    gemm_mma<1><<<dim3(DIM / 128, TOK / 128), 256>>>(
        attnb, wproj, projb, x, x2, nullptr, DIM, DIM);
    // 5. LN2 -> bf16
    ln_kernel<false><<<TOK / 8, 256>>>(x2, n2w, n2b, h2b);
    // 6. FC1 + GELU -> bf16
    gemm_mma<2><<<dim3(HIDDEN / 128, TOK / 128), 256>>>(
        h2b, wfc1, fc1b, nullptr, nullptr, hbufb, DIM, HIDDEN);
    // 7. FC2 + bias + residual -> final fp32
    gemm_mma<3><<<dim3(DIM / 128, TOK / 128), 256>>>(
        hbufb, wfc2, fc2b, x2, outp, nullptr, HIDDEN, DIM);
}

// round 9
// speedup vs baseline: 5.4441x; 1.4585x over previous
#include <cuda_runtime.h>
#include <cuda_bf16.h>
#include <math.h>
#include <stdint.h>

// ---------------------------------------------------------------------------
// Swin block: GEMMs + attention via mma.sync bf16 (fp32 accum), LN fp32.
// B=32, H=W=56, DIM=256, HEADS=8, WS=7, SHIFT=3, N=49, NW=64, HEAD_DIM=32.
// ---------------------------------------------------------------------------

#define TOK      100352
#define DIM      256
#define HIDDEN   1024
#define QKVDIM   768
#define HEADS    8
#define HEAD_DIM 32
#define NTOK     49
#define HW       3136
#define SHIFT    3

typedef __nv_bfloat16 bf16;

// ------------------------- scratch (device globals) ------------------------
__device__ __align__(16) bf16  g_hwin_b[(size_t)TOK * DIM];
__device__ __align__(16) bf16  g_qkv_b [(size_t)TOK * QKVDIM];
__device__ __align__(16) bf16  g_attn_b[(size_t)TOK * DIM];
__device__ __align__(16) float g_x2    [(size_t)TOK * DIM];
__device__ __align__(16) bf16  g_h2_b  [(size_t)TOK * DIM];
__device__ __align__(16) bf16  g_hbuf_b[(size_t)TOK * HIDDEN];
__device__ __align__(16) bf16  g_wqkv_b [QKVDIM * DIM];
__device__ __align__(16) bf16  g_wproj_b[DIM * DIM];
__device__ __align__(16) bf16  g_wfc1_b [HIDDEN * DIM];
__device__ __align__(16) bf16  g_wfc2_b [DIM * HIDDEN];

// ------------------------------ PTX helpers --------------------------------
__device__ __forceinline__ uint32_t smem_u32(const void* p) {
    uint32_t a;
    asm("{ .reg .u64 t; cvta.to.shared.u64 t, %1; cvt.u32.u64 %0, t; }"
        : "=r"(a) : "l"(p));
    return a;
}
__device__ __forceinline__ void cp_async16(uint32_t dst, const void* src) {
    asm volatile("cp.async.cg.shared.global [%0], [%1], 16;"
                 :: "r"(dst), "l"(src));
}
#define CP_COMMIT() asm volatile("cp.async.commit_group;")
#define CP_WAIT(n)  asm volatile("cp.async.wait_group %0;" :: "n"(n))

__device__ __forceinline__ void ldsm_x4(uint32_t& r0, uint32_t& r1,
                                        uint32_t& r2, uint32_t& r3, uint32_t a) {
    asm volatile("ldmatrix.sync.aligned.m8n8.x4.shared.b16 {%0,%1,%2,%3}, [%4];"
                 : "=r"(r0), "=r"(r1), "=r"(r2), "=r"(r3) : "r"(a));
}
__device__ __forceinline__ void ldsm_x4t(uint32_t& r0, uint32_t& r1,
                                         uint32_t& r2, uint32_t& r3, uint32_t a) {
    asm volatile("ldmatrix.sync.aligned.m8n8.x4.trans.shared.b16 {%0,%1,%2,%3}, [%4];"
                 : "=r"(r0), "=r"(r1), "=r"(r2), "=r"(r3) : "r"(a));
}
__device__ __forceinline__ void mma16816(float* d, const uint32_t* a,
                                         const uint32_t* b) {
    asm volatile(
        "mma.sync.aligned.m16n8k16.row.col.f32.bf16.bf16.f32 "
        "{%0,%1,%2,%3}, {%4,%5,%6,%7}, {%8,%9}, {%0,%1,%2,%3};"
        : "+f"(d[0]), "+f"(d[1]), "+f"(d[2]), "+f"(d[3])
        : "r"(a[0]), "r"(a[1]), "r"(a[2]), "r"(a[3]), "r"(b[0]), "r"(b[1]));
}
__device__ __forceinline__ uint32_t packbf(float lo, float hi) {
    uint32_t r;
    asm("cvt.rn.bf16x2.f32 %0, %1, %2;" : "=r"(r) : "f"(hi), "f"(lo));
    return r;
}

// ---------------------------------------------------------------------------
// LayerNorm -> bf16. REMAP: gather with cyclic shift + window partition.
// ---------------------------------------------------------------------------
template <bool REMAP>
__global__ void ln_kernel(const float* __restrict__ in,
                          const float* __restrict__ w,
                          const float* __restrict__ b,
                          bf16* __restrict__ out)
{
    int warp = threadIdx.x >> 5;
    int lane = threadIdx.x & 31;
    int row  = blockIdx.x * 8 + warp;

    const float* src;
    if (REMAP) {
        int bz = row / HW;
        int r  = row - bz * HW;
        int wI = r / NTOK;
        int t2 = r - wI * NTOK;
        int wh = wI >> 3, ww = wI & 7;
        int i  = t2 / 7,  j  = t2 - (t2 / 7) * 7;
        int sh = (wh * 7 + i + SHIFT) % 56;
        int sw = (ww * 7 + j + SHIFT) % 56;
        src = in + ((size_t)bz * HW + sh * 56 + sw) * DIM;
    } else {
        src = in + (size_t)row * DIM;
    }

    float v[8];
    float s = 0.f, ss = 0.f;
#pragma unroll
    for (int k = 0; k < 8; k++) {
        v[k] = src[lane + 32 * k];
        s  += v[k];
        ss += v[k] * v[k];
    }
#pragma unroll
    for (int o = 16; o; o >>= 1) {
        s  += __shfl_xor_sync(0xffffffffu, s,  o);
        ss += __shfl_xor_sync(0xffffffffu, ss, o);
    }
    float mu   = s * (1.f / DIM);
    float var  = ss * (1.f / DIM) - mu * mu;
    float rstd = rsqrtf(var + 1e-5f);

    bf16* dst = out + (size_t)row * DIM;
#pragma unroll
    for (int k = 0; k < 8; k++) {
        int c = lane + 32 * k;
        dst[c] = __float2bfloat16((v[k] - mu) * rstd * w[c] + b[c]);
    }
}

__global__ void cvt_kernel(const float* __restrict__ in,
                           bf16* __restrict__ out, int n)
{
    int i = blockIdx.x * 256 + threadIdx.x;
    if (i < n) out[i] = __float2bfloat16(in[i]);
}

// ---------------------------------------------------------------------------
// bf16 mma.sync GEMM: C[m,n] = sum_k A[m,k]*W[n,k] (+ epilogue)
// BM=BN=128, BK=32, 256 thr (2x4 warps; 64x32/warp), 2-stage cp.async.
// EPI: 0 qkv(+bias -> bf16)  1 proj(+bias,scatter+residual)
//      2 fc1(+bias,gelu->bf16)  3 fc2(+bias+residual)
// ---------------------------------------------------------------------------
#define STRIDE 40   // bf16 per smem row (32 + 8 pad)

template <int EPI>
__global__ void __launch_bounds__(256)
gemm_mma(const bf16* __restrict__ A, const bf16* __restrict__ W,
         const float* __restrict__ bias, const float* __restrict__ extra,
         float* __restrict__ out, bf16* __restrict__ outb,
         int K, int Ntot)
{
    __shared__ bf16 As[2][128][STRIDE];
    __shared__ bf16 Bs[2][128][STRIDE];

    int tid    = threadIdx.x;
    int lane   = tid & 31;
    int wid    = tid >> 5;
    int warp_m = wid & 1;
    int warp_n = wid >> 1;
    int m0     = blockIdx.y * 128;
    int n0     = blockIdx.x * 128;

    int lr = tid >> 2;
    int lc = (tid & 3) << 3;

    float c[4][4][4];
#pragma unroll
    for (int i = 0; i < 4; i++)
#pragma unroll
        for (int j = 0; j < 4; j++)
#pragma unroll
            for (int k = 0; k < 4; k++) c[i][j][k] = 0.f;

    int nk = K >> 5;

    {
#pragma unroll
        for (int t = 0; t < 2; t++) {
            int r = lr + t * 64;
            cp_async16(smem_u32(&As[0][r][lc]), A + (size_t)(m0 + r) * K + lc);
            cp_async16(smem_u32(&Bs[0][r][lc]), W + (size_t)(n0 + r) * K + lc);
        }
        CP_COMMIT();
    }

    int a_row  = warp_m * 64 + (lane & 15);
    int a_koff = (lane >> 4) << 3;
    int b_row0 = warp_n * 32 + (lane & 7) + ((lane >> 4) << 3);
    int b_koff = ((lane >> 3) & 1) << 3;

    for (int kk = 0; kk < nk; kk++) {
        int st = kk & 1;
        if (kk + 1 < nk) {
            int kb = (kk + 1) << 5;
#pragma unroll
            for (int t = 0; t < 2; t++) {
                int r = lr + t * 64;
                cp_async16(smem_u32(&As[st ^ 1][r][lc]),
                           A + (size_t)(m0 + r) * K + kb + lc);
                cp_async16(smem_u32(&Bs[st ^ 1][r][lc]),
                           W + (size_t)(n0 + r) * K + kb + lc);
            }
            CP_COMMIT();
            CP_WAIT(1);
        } else {
            CP_WAIT(0);
        }
        __syncthreads();

#pragma unroll
        for (int ks = 0; ks < 2; ks++) {
            uint32_t a[4][4];
            uint32_t b[4][2];
#pragma unroll
            for (int mt = 0; mt < 4; mt++)
                ldsm_x4(a[mt][0], a[mt][1], a[mt][2], a[mt][3],
                        smem_u32(&As[st][a_row + mt * 16][ks * 16 + a_koff]));
#pragma unroll
            for (int np = 0; np < 2; np++)
                ldsm_x4(b[np * 2][0], b[np * 2][1], b[np * 2 + 1][0], b[np * 2 + 1][1],
                        smem_u32(&Bs[st][b_row0 + np * 16][ks * 16 + b_koff]));
#pragma unroll
            for (int mt = 0; mt < 4; mt++)
#pragma unroll
                for (int nt = 0; nt < 4; nt++)
                    mma16816(c[mt][nt], a[mt], b[nt]);
        }
        __syncthreads();
    }

    // ------------------------------- epilogue -------------------------------
    int gid = lane >> 2;
    int qid = lane & 3;

#pragma unroll
    for (int mt = 0; mt < 4; mt++) {
        int r0 = m0 + warp_m * 64 + mt * 16 + gid;
        int r1 = r0 + 8;
        size_t base0, base1;
        if (EPI == 1) {
#pragma unroll
            for (int h = 0; h < 2; h++) {
                int row = h ? r1 : r0;
                int bz = row / HW;
                int r  = row - bz * HW;
                int wI = r / NTOK;
                int t2 = r - wI * NTOK;
                int wh = wI >> 3, ww = wI & 7;
                int ii = t2 / 7,  jj = t2 - (t2 / 7) * 7;
                int sh = (wh * 7 + ii + SHIFT) % 56;
                int sw = (ww * 7 + jj + SHIFT) % 56;
                size_t d = ((size_t)bz * HW + sh * 56 + sw) * DIM;
                if (h) base1 = d; else base0 = d;
            }
        } else {
            base0 = (size_t)r0 * Ntot;
            base1 = (size_t)r1 * Ntot;
        }
#pragma unroll
        for (int nt = 0; nt < 4; nt++) {
            int col = n0 + warp_n * 32 + nt * 8 + qid * 2;
            float b0 = bias[col], b1 = bias[col + 1];
            float v00 = c[mt][nt][0] + b0, v01 = c[mt][nt][1] + b1;
            float v10 = c[mt][nt][2] + b0, v11 = c[mt][nt][3] + b1;
            if (EPI == 0) {
                *(uint32_t*)(outb + base0 + col) = packbf(v00, v01);
                *(uint32_t*)(outb + base1 + col) = packbf(v10, v11);
            } else if (EPI == 1) {
                out[base0 + col]     = v00 + extra[base0 + col];
                out[base0 + col + 1] = v01 + extra[base0 + col + 1];
                out[base1 + col]     = v10 + extra[base1 + col];
                out[base1 + col + 1] = v11 + extra[base1 + col + 1];
            } else if (EPI == 2) {
                const float isq2 = 0.70710678118654752f;
                float g00 = 0.5f * v00 * (1.f + erff(v00 * isq2));
                float g01 = 0.5f * v01 * (1.f + erff(v01 * isq2));
                float g10 = 0.5f * v10 * (1.f + erff(v10 * isq2));
                float g11 = 0.5f * v11 * (1.f + erff(v11 * isq2));
                *(uint32_t*)(outb + base0 + col) = packbf(g00, g01);
                *(uint32_t*)(outb + base1 + col) = packbf(g10, g11);
            } else {
                *(float2*)(out + base0 + col) =
                    make_float2(v00 + extra[base0 + col], v01 + extra[base0 + col + 1]);
                *(float2*)(out + base1 + col) =
                    make_float2(v10 + extra[base1 + col], v11 + extra[base1 + col + 1]);
            }
        }
    }
}

// ---------------------------------------------------------------------------
// Windowed attention via mma.sync. One block per (window, head), 128 thr.
// Pads 49 -> 64 on all token dims; masked cols get -1e30 before softmax.
// Probability C-frags re-packed directly as A-frags for the AV mma.
// ---------------------------------------------------------------------------
__global__ void __launch_bounds__(128)
attn_mma(const bf16* __restrict__ qkv, const float* __restrict__ rpb,
         const int* __restrict__ relidx, const float* __restrict__ mask,
         bf16* __restrict__ out)
{
    __shared__ bf16 qs[64][STRIDE];
    __shared__ bf16 ks[64][STRIDE];
    __shared__ bf16 vs[64][STRIDE];
    __shared__ float rpb_s[169];

    int blk  = blockIdx.x;
    int head = blk & 7;
    int win  = blk >> 3;
    int tid  = threadIdx.x;
    int lane = tid & 31;
    int warp = tid >> 5;

    // zero pad rows 49..63 (600 bf16 = 300 u32 per array)
    for (int i = tid; i < 300; i += 128) {
        ((uint32_t*)qs)[980 + i] = 0;
        ((uint32_t*)ks)[980 + i] = 0;
        ((uint32_t*)vs)[980 + i] = 0;
    }
    // load q/k/v tiles (49 x 32 bf16 each)
    const bf16* base = qkv + (size_t)win * NTOK * QKVDIM + head * HEAD_DIM;
    for (int idx = tid; idx < NTOK * 4; idx += 128) {
        int t  = idx >> 2;
        int ch = (idx & 3) << 3;
        const bf16* p = base + (size_t)t * QKVDIM + ch;
        *(uint4*)&qs[t][ch] = *(const uint4*)(p);
        *(uint4*)&ks[t][ch] = *(const uint4*)(p + 256);
        *(uint4*)&vs[t][ch] = *(const uint4*)(p + 512);
    }
    for (int i = tid; i < 169; i += 128) rpb_s[i] = rpb[i * HEADS + head];
    __syncthreads();

    int wm  = warp * 16;
    int gid = lane >> 2;
    int qid = lane & 3;

    // ---- scores S = q @ k^T : M16 per warp x N64, K=32 -------------------
    uint32_t aq[2][4];
#pragma unroll
    for (int kt = 0; kt < 2; kt++)
        ldsm_x4(aq[kt][0], aq[kt][1], aq[kt][2], aq[kt][3],
                smem_u32(&qs[wm + (lane & 15)][kt * 16 + ((lane >> 4) << 3)]));

    uint32_t bk[2][8][2];
#pragma unroll
    for (int kt = 0; kt < 2; kt++)
#pragma unroll
        for (int nt2 = 0; nt2 < 4; nt2++)
            ldsm_x4(bk[kt][nt2 * 2][0], bk[kt][nt2 * 2][1],
                    bk[kt][nt2 * 2 + 1][0], bk[kt][nt2 * 2 + 1][1],
                    smem_u32(&ks[nt2 * 16 + (lane & 7) + ((lane >> 4) << 3)]
                                [kt * 16 + (((lane >> 3) & 1) << 3)]));

    float c[8][4];
#pragma unroll
    for (int nt = 0; nt < 8; nt++)
#pragma unroll
        for (int e = 0; e < 4; e++) c[nt][e] = 0.f;
#pragma unroll
    for (int kt = 0; kt < 2; kt++)
#pragma unroll
        for (int nt = 0; nt < 8; nt++)
            mma16816(c[nt], aq[kt], bk[kt][nt]);

    // ---- scale + rel-pos bias + shift mask --------------------------------
    const float scale = 0.17677669529663687f;  // 1/sqrt(32)
    const float* mrow = mask + (size_t)(win & 63) * (NTOK * NTOK);
#pragma unroll
    for (int nt = 0; nt < 8; nt++) {
        int j0 = nt * 8 + qid * 2;
#pragma unroll
        for (int e = 0; e < 4; e++) {
            int i = wm + gid + ((e >> 1) << 3);
            int j = j0 + (e & 1);
            if (j < NTOK && i < NTOK) {
                int ij = i * NTOK + j;
                c[nt][e] = c[nt][e] * scale + rpb_s[relidx[ij]] + mrow[ij];
            } else {
                c[nt][e] = -1e30f;
            }
        }
    }

    // ---- softmax (rows live in 4 lanes: qid = lane&3) ---------------------
    float mx0 = -1e30f, mx1 = -1e30f;
#pragma unroll
    for (int nt = 0; nt < 8; nt++) {
        mx0 = fmaxf(mx0, fmaxf(c[nt][0], c[nt][1]));
        mx1 = fmaxf(mx1, fmaxf(c[nt][2], c[nt][3]));
    }
#pragma unroll
    for (int o = 1; o <= 2; o <<= 1) {
        mx0 = fmaxf(mx0, __shfl_xor_sync(0xffffffffu, mx0, o));
        mx1 = fmaxf(mx1, __shfl_xor_sync(0xffffffffu, mx1, o));
    }
    float s0 = 0.f, s1 = 0.f;
#pragma unroll
    for (int nt = 0; nt < 8; nt++) {
        c[nt][0] = __expf(c[nt][0] - mx0); s0 += c[nt][0];
        c[nt][1] = __expf(c[nt][1] - mx0); s0 += c[nt][1];
        c[nt][2] = __expf(c[nt][2] - mx1); s1 += c[nt][2];
        c[nt][3] = __expf(c[nt][3] - mx1); s1 += c[nt][3];
    }
#pragma unroll
    for (int o = 1; o <= 2; o <<= 1) {
        s0 += __shfl_xor_sync(0xffffffffu, s0, o);
        s1 += __shfl_xor_sync(0xffffffffu, s1, o);
    }
    float inv0 = 1.f / s0, inv1 = 1.f / s1;
#pragma unroll
    for (int nt = 0; nt < 8; nt++) {
        c[nt][0] *= inv0; c[nt][1] *= inv0;
        c[nt][2] *= inv1; c[nt][3] *= inv1;
    }

    // ---- repack prob C-frags as A-frags (bf16) ----------------------------
    uint32_t ap[4][4];
#pragma unroll
    for (int kt = 0; kt < 4; kt++) {
        ap[kt][0] = packbf(c[2 * kt][0],     c[2 * kt][1]);
        ap[kt][1] = packbf(c[2 * kt][2],     c[2 * kt][3]);
        ap[kt][2] = packbf(c[2 * kt + 1][0], c[2 * kt + 1][1]);
        ap[kt][3] = packbf(c[2 * kt + 1][2], c[2 * kt + 1][3]);
    }

    // ---- O = P @ V : M16 x N32, K=64 (V row-major -> ldmatrix.trans) ------
    float o[4][4];
#pragma unroll
    for (int nt = 0; nt < 4; nt++)
#pragma unroll
        for (int e = 0; e < 4; e++) o[nt][e] = 0.f;
#pragma unroll
    for (int kt = 0; kt < 4; kt++) {
#pragma unroll
        for (int ng = 0; ng < 2; ng++) {
            uint32_t r0, r1, r2, r3;
            ldsm_x4t(r0, r1, r2, r3,
                smem_u32(&vs[kt * 16 + (lane & 7) + (((lane >> 3) & 1) << 3)]
                            [ng * 16 + ((lane >> 4) << 3)]));
            uint32_t bv0[2] = {r0, r1};
            uint32_t bv1[2] = {r2, r3};
            mma16816(o[ng * 2],     ap[kt], bv0);
            mma16816(o[ng * 2 + 1], ap[kt], bv1);
        }
    }

    // ---- write output (rows < 49 only) ------------------------------------
    int i0 = wm + gid;
    int i1 = i0 + 8;
    size_t ob0 = ((size_t)win * NTOK + i0) * DIM + head * HEAD_DIM;
    size_t ob1 = ((size_t)win * NTOK + i1) * DIM + head * HEAD_DIM;
#pragma unroll
    for (int nt = 0; nt < 4; nt++) {
        int n = nt * 8 + qid * 2;
        if (i0 < NTOK) *(uint32_t*)(out + ob0 + n) = packbf(o[nt][0], o[nt][1]);
        if (i1 < NTOK) *(uint32_t*)(out + ob1 + n) = packbf(o[nt][2], o[nt][3]);
    }
}

// ---------------------------------------------------------------------------
extern "C" void kernel_launch(void* const* d_in, const int* in_sizes, int n_in,
                              void* d_out, int out_size)
{
    const float* x     = (const float*)d_in[0];
    const float* n1w   = (const float*)d_in[1];
    const float* n1b   = (const float*)d_in[2];
    const float* qkvw  = (const float*)d_in[3];
    const float* qkvb  = (const float*)d_in[4];
    const float* rpb   = (const float*)d_in[5];
    const float* projw = (const float*)d_in[6];
    const float* projb = (const float*)d_in[7];
    const float* n2w   = (const float*)d_in[8];
    const float* n2b   = (const float*)d_in[9];
    const float* fc1w  = (const float*)d_in[10];
    const float* fc1b  = (const float*)d_in[11];
    const float* fc2w  = (const float*)d_in[12];
    const float* fc2b  = (const float*)d_in[13];
    const int*   ridx  = (const int*)d_in[14];
    const float* amask = (const float*)d_in[15];
    float* outp = (float*)d_out;

    bf16 *hwin, *qkvb16, *attnb, *h2b, *hbufb, *wqkv, *wproj, *wfc1, *wfc2;
    float *x2;
    cudaGetSymbolAddress((void**)&hwin,   g_hwin_b);
    cudaGetSymbolAddress((void**)&qkvb16, g_qkv_b);
    cudaGetSymbolAddress((void**)&attnb,  g_attn_b);
    cudaGetSymbolAddress((void**)&x2,     g_x2);
    cudaGetSymbolAddress((void**)&h2b,    g_h2_b);
    cudaGetSymbolAddress((void**)&hbufb,  g_hbuf_b);
    cudaGetSymbolAddress((void**)&wqkv,   g_wqkv_b);
    cudaGetSymbolAddress((void**)&wproj,  g_wproj_b);
    cudaGetSymbolAddress((void**)&wfc1,   g_wfc1_b);
    cudaGetSymbolAddress((void**)&wfc2,   g_wfc2_b);

    // weight conversion
    cvt_kernel<<<(QKVDIM * DIM + 255) / 256, 256>>>(qkvw,  wqkv,  QKVDIM * DIM);
    cvt_kernel<<<(DIM * DIM + 255) / 256, 256>>>(projw, wproj, DIM * DIM);
    cvt_kernel<<<(HIDDEN * DIM + 255) / 256, 256>>>(fc1w,  wfc1,  HIDDEN * DIM);
    cvt_kernel<<<(DIM * HIDDEN + 255) / 256, 256>>>(fc2w,  wfc2,  DIM * HIDDEN);

    // 1. LN1 + shift + window partition -> bf16
    ln_kernel<true><<<TOK / 8, 256>>>(x, n1w, n1b, hwin);
    // 2. QKV GEMM [TOK,256] x [768,256]^T -> bf16
    gemm_mma<0><<<dim3(QKVDIM / 128, TOK / 128), 256>>>(
        hwin, wqkv, qkvb, nullptr, nullptr, qkvb16, DIM, QKVDIM);
    // 3. windowed attention (mma.sync) -> bf16
    attn_mma<<<2048 * HEADS, 128>>>(qkvb16, rpb, ridx, amask, attnb);
    // 4. proj GEMM + window-reverse scatter + residual -> x2
    gemm_mma<1><<<dim3(DIM / 128, TOK / 128), 256>>>(
        attnb, wproj, projb, x, x2, nullptr, DIM, DIM);
    // 5. LN2 -> bf16
    ln_kernel<false><<<TOK / 8, 256>>>(x2, n2w, n2b, h2b);
    // 6. FC1 + GELU -> bf16
    gemm_mma<2><<<dim3(HIDDEN / 128, TOK / 128), 256>>>(
        h2b, wfc1, fc1b, nullptr, nullptr, hbufb, DIM, HIDDEN);
    // 7. FC2 + bias + residual -> final fp32
    gemm_mma<3><<<dim3(DIM / 128, TOK / 128), 256>>>(
        hbufb, wfc2, fc2b, x2, outp, nullptr, HIDDEN, DIM);
}